// round 4
// baseline (speedup 1.0000x reference)
#include <cuda_runtime.h>
#include <math.h>

// Problem shape (fixed by the reference)
#define BB   32
#define CC   256
#define HH   128
#define WW   128
#define HWSZ (HH * WW)       // 16384
#define HW4  (HWSZ / 4)      // 4096 float4 per (b) spatial plane

// Scratch (allocation-free: __device__ globals). 3 * 2 MiB = 6 MiB.
__device__ float g_avg[BB * HWSZ];
__device__ float g_max[BB * HWSZ];
__device__ float g_gate[BB * HWSZ];

// ---------------------------------------------------------------------------
// Kernel 1: channel-wise mean + max of y.  y: [B, C, H, W] fp32.
// Thread t owns one float4 of spatial positions; loops over C (stride HW4).
// Coalesced 128B per warp per iteration; unroll 8 for MLP.
// ---------------------------------------------------------------------------
__global__ __launch_bounds__(256) void reduce_bc(const float* __restrict__ y) {
    const int b = blockIdx.y;
    const int t = blockIdx.x * blockDim.x + threadIdx.x;   // 0 .. HW4-1

    const float4* yp = reinterpret_cast<const float4*>(y)
                     + (size_t)b * CC * HW4 + t;

    float4 s = make_float4(0.f, 0.f, 0.f, 0.f);
    float4 m = make_float4(-INFINITY, -INFINITY, -INFINITY, -INFINITY);

    #pragma unroll 8
    for (int c = 0; c < CC; ++c) {
        float4 v = yp[(size_t)c * HW4];
        s.x += v.x; s.y += v.y; s.z += v.z; s.w += v.w;
        m.x = fmaxf(m.x, v.x); m.y = fmaxf(m.y, v.y);
        m.z = fmaxf(m.z, v.z); m.w = fmaxf(m.w, v.w);
    }

    const float inv = 1.0f / (float)CC;
    float4 a = make_float4(s.x * inv, s.y * inv, s.z * inv, s.w * inv);

    reinterpret_cast<float4*>(g_avg)[(size_t)b * HW4 + t] = a;
    reinterpret_cast<float4*>(g_max)[(size_t)b * HW4 + t] = m;
}

// ---------------------------------------------------------------------------
// Kernel 2: 3x3 conv over the 2-channel [avg; max] map, zero padding,
// then sigmoid -> gate[B, H, W].  Inputs are L2-resident (4 MiB).
// conv_w layout: [1, 2, 3, 3] row-major -> w[ic][i][j] = cw[ic*9 + i*3 + j].
// jax conv_general_dilated with NCHW/OIHW is correlation (no kernel flip).
// ---------------------------------------------------------------------------
__global__ __launch_bounds__(256) void conv_gate(const float* __restrict__ cw) {
    const int idx = blockIdx.x * blockDim.x + threadIdx.x;
    if (idx >= BB * HWSZ) return;

    const int b  = idx >> 14;          // / HWSZ
    const int hw = idx & (HWSZ - 1);
    const int h  = hw >> 7;            // / WW
    const int w  = hw & (WW - 1);

    float wt[18];
    #pragma unroll
    for (int i = 0; i < 18; ++i) wt[i] = cw[i];

    float acc = 0.0f;
    #pragma unroll
    for (int di = -1; di <= 1; ++di) {
        const int hh = h + di;
        if (hh < 0 || hh >= HH) continue;
        #pragma unroll
        for (int dj = -1; dj <= 1; ++dj) {
            const int ww2 = w + dj;
            if (ww2 < 0 || ww2 >= WW) continue;
            const int off = b * HWSZ + hh * WW + ww2;
            const int k   = (di + 1) * 3 + (dj + 1);
            acc = fmaf(g_avg[off], wt[k],     acc);
            acc = fmaf(g_max[off], wt[9 + k], acc);
        }
    }
    g_gate[idx] = 1.0f / (1.0f + expf(-acc));
}

// ---------------------------------------------------------------------------
// Kernel 3: out = x * gate (gate broadcast over C).
// Block = (hw-chunk of 1024 floats, batch b); threads loop over all C so each
// thread's gate float4 is loaded exactly once (gate traffic = 2 MiB total).
// ---------------------------------------------------------------------------
__global__ __launch_bounds__(256) void apply_gate(const float* __restrict__ x,
                                                  float* __restrict__ out) {
    const int b  = blockIdx.y;
    const int t4 = blockIdx.x * 256 + threadIdx.x;   // float4 index in plane

    const float4 g = reinterpret_cast<const float4*>(g_gate)[(size_t)b * HW4 + t4];

    const float4* xp = reinterpret_cast<const float4*>(x)
                     + (size_t)b * CC * HW4 + t4;
    float4* op = reinterpret_cast<float4*>(out)
               + (size_t)b * CC * HW4 + t4;

    #pragma unroll 8
    for (int c = 0; c < CC; ++c) {
        float4 v = xp[(size_t)c * HW4];
        v.x *= g.x; v.y *= g.y; v.z *= g.z; v.w *= g.w;
        op[(size_t)c * HW4] = v;
    }
}

// ---------------------------------------------------------------------------
// Launch. Inputs (metadata order): d_in[0]=x [B,C,H,W] f32,
// d_in[1]=y [B,C,H,W] f32, d_in[2]=conv_w [1,2,3,3] f32. Output f32 [B,C,H,W].
// ---------------------------------------------------------------------------
extern "C" void kernel_launch(void* const* d_in, const int* in_sizes, int n_in,
                              void* d_out, int out_size) {
    (void)in_sizes; (void)n_in; (void)out_size;
    const float* x  = (const float*)d_in[0];
    const float* y  = (const float*)d_in[1];
    const float* cw = (const float*)d_in[2];
    float* out = (float*)d_out;

    dim3 rgrid(HW4 / 256, BB);           // (16, 32) = 512 CTAs
    reduce_bc<<<rgrid, 256>>>(y);

    conv_gate<<<(BB * HWSZ + 255) / 256, 256>>>(cw);

    dim3 agrid(HW4 / 256, BB);           // (16, 32) = 512 CTAs
    apply_gate<<<agrid, 256>>>(x, out);
}